// round 1
// baseline (speedup 1.0000x reference)
#include <cuda_runtime.h>
#include <math_constants.h>

#define BB   2
#define NN   32768
#define NCC  1024
#define SS   32
#define MM   (NCC*SS)          // 32768

#define K2_THREADS 128
#define K2_R       8
#define K2_TM      (K2_THREADS*K2_R)   // 1024 sphere points per block
#define K2_NSPLIT  8
#define K2_NSLICE  (NN/K2_NSPLIT)      // 4096
#define K2_TILE    512

// Scratch (no allocations allowed) ------------------------------------------
__device__ float4       g_xyzp[BB*NN];    // (x,y,z, x^2+y^2+z^2)
__device__ float4       g_ctrp[BB*NCC];   // same packing for centers
__device__ unsigned int g_minsq[BB*MM];   // min squared dist, as uint bits (>=0 floats)
__device__ float        g_acc[4];         // [b] = sum|min(r-cd,0)| ; [2+b] = sum of max cd

// ---------------------------------------------------------------------------
__inline__ __device__ float blockReduceSum(float v) {
    __shared__ float sw[32];
    #pragma unroll
    for (int o = 16; o > 0; o >>= 1) v += __shfl_down_sync(0xffffffffu, v, o);
    int lane = threadIdx.x & 31, w = threadIdx.x >> 5;
    if (lane == 0) sw[w] = v;
    __syncthreads();
    int nw = blockDim.x >> 5;
    v = (threadIdx.x < nw) ? sw[threadIdx.x] : 0.0f;
    if (w == 0) {
        #pragma unroll
        for (int o = 16; o > 0; o >>= 1) v += __shfl_down_sync(0xffffffffu, v, o);
    }
    return v;
}

// Pack inputs + init scratch (65536 threads covers BB*NN == BB*MM) -----------
__global__ void k_prep(const float* __restrict__ xyz, const float* __restrict__ ctr) {
    int i = blockIdx.x * blockDim.x + threadIdx.x;
    if (i < BB*NN) {
        float x = xyz[3*i+0], y = xyz[3*i+1], z = xyz[3*i+2];
        g_xyzp[i] = make_float4(x, y, z, x*x + y*y + z*z);
        g_minsq[i] = 0x7F800000u;   // +inf
    }
    if (i < BB*NCC) {
        float x = ctr[3*i+0], y = ctr[3*i+1], z = ctr[3*i+2];
        g_ctrp[i] = make_float4(x, y, z, x*x + y*y + z*z);
    }
    if (i < 4) g_acc[i] = 0.0f;
}

// Part 1: point -> nearest center, accumulate |min(r - cd, 0)| ----------------
__global__ void k_p2c(const float* __restrict__ radius) {
    __shared__ float4 shc[NCC];
    const int b = blockIdx.y;
    const int n = blockIdx.x * blockDim.x + threadIdx.x;
    for (int i = threadIdx.x; i < NCC; i += blockDim.x)
        shc[i] = g_ctrp[b*NCC + i];
    __syncthreads();

    float4 q = g_xyzp[b*NN + n];
    float ax = -2.0f*q.x, ay = -2.0f*q.y, az = -2.0f*q.z;
    float tmin = CUDART_INF_F;
    int idx = 0;
    #pragma unroll 4
    for (int c = 0; c < NCC; ++c) {
        float4 p = shc[c];
        float t = fmaf(ax, p.x, p.w);
        t = fmaf(ay, p.y, t);
        t = fmaf(az, p.z, t);
        if (t < tmin) { tmin = t; idx = c; }   // strict < : first-min, matches argmin
    }
    float cd = sqrtf(fmaxf(tmin + q.w, 1e-12f));
    float contrib = fmaxf(cd - radius[b*NCC + idx], 0.0f); // |min(r-cd,0)|
    float s = blockReduceSum(contrib);
    if (threadIdx.x == 0) atomicAdd(&g_acc[b], s);
}

// Part 2 (dominant): sphere point -> min over xyz (tiled, register-blocked) ---
__global__ void __launch_bounds__(K2_THREADS)
k_sp2p(const float* __restrict__ sp) {
    __shared__ float4 shp[K2_TILE];
    const int b     = blockIdx.z;
    const int nbase = blockIdx.y * K2_NSLICE;
    const int mbase = blockIdx.x * K2_TM;
    const int tid   = threadIdx.x;

    float ax[K2_R], ay[K2_R], az[K2_R], nq[K2_R], mn[K2_R];
    #pragma unroll
    for (int r = 0; r < K2_R; ++r) {
        int m = mbase + tid*K2_R + r;
        const float* p = sp + ((long long)b*MM + m) * 3;
        float x = p[0], y = p[1], z = p[2];
        ax[r] = -2.0f*x; ay[r] = -2.0f*y; az[r] = -2.0f*z;
        nq[r] = x*x + y*y + z*z;
        mn[r] = CUDART_INF_F;
    }

    const float4* xb = g_xyzp + b*NN + nbase;
    for (int jt = 0; jt < K2_NSLICE; jt += K2_TILE) {
        for (int i = tid; i < K2_TILE; i += K2_THREADS)
            shp[i] = xb[jt + i];
        __syncthreads();
        #pragma unroll 4
        for (int j = 0; j < K2_TILE; ++j) {
            float4 p = shp[j];            // LDS.128 broadcast
            #pragma unroll
            for (int r = 0; r < K2_R; ++r) {
                float t = fmaf(ax[r], p.x, p.w);
                t = fmaf(ay[r], p.y, t);
                t = fmaf(az[r], p.z, t);
                mn[r] = fminf(mn[r], t);
            }
        }
        __syncthreads();
    }

    #pragma unroll
    for (int r = 0; r < K2_R; ++r) {
        float sq = fmaxf(mn[r] + nq[r], 0.0f);   // >=0 so uint order == float order
        atomicMin(&g_minsq[b*MM + mbase + tid*K2_R + r], __float_as_uint(sq));
    }
}

// Part 2 epilogue: max over S per center, sum over centers --------------------
__global__ void k_c2p() {
    const int b = blockIdx.y;
    const int c = blockIdx.x * blockDim.x + threadIdx.x;
    const unsigned int* base = g_minsq + b*MM + c*SS;
    float mx = 0.0f;
    #pragma unroll
    for (int s = 0; s < SS; ++s) {
        float sq = __uint_as_float(base[s]);
        mx = fmaxf(mx, sqrtf(fmaxf(sq, 1e-12f)));
    }
    float s = blockReduceSum(mx);
    if (threadIdx.x == 0) atomicAdd(&g_acc[2 + b], s);
}

// Final scalar ----------------------------------------------------------------
__global__ void k_final(float* out) {
    float r = 0.0f;
    #pragma unroll
    for (int b = 0; b < BB; ++b)
        r += g_acc[b] * (1.0f/NN) + g_acc[2 + b] * (1.0f/NCC);
    out[0] = r * (1.0f/BB);
}

// ---------------------------------------------------------------------------
extern "C" void kernel_launch(void* const* d_in, const int* in_sizes, int n_in,
                              void* d_out, int out_size) {
    const float* centers = (const float*)d_in[0];
    const float* radius  = (const float*)d_in[1];
    const float* xyz     = (const float*)d_in[2];
    const float* sp      = (const float*)d_in[3];
    float* out = (float*)d_out;

    k_prep<<<(BB*NN)/256, 256>>>(xyz, centers);
    k_p2c<<<dim3(NN/256, BB), 256>>>(radius);
    k_sp2p<<<dim3(MM/K2_TM, K2_NSPLIT, BB), K2_THREADS>>>(sp);
    k_c2p<<<dim3(NCC/256, BB), 256>>>();
    k_final<<<1, 1>>>(out);
}

// round 2
// speedup vs baseline: 1.0060x; 1.0060x over previous
#include <cuda_runtime.h>
#include <math_constants.h>

#define BB   2
#define NN   32768
#define NCC  1024
#define SS   32
#define MM   (NCC*SS)          // 32768

#define K2_THREADS 128
#define K2_R       8                     // sphere points per thread (4 packed pairs)
#define K2_TM      (K2_THREADS*K2_R)     // 1024 sphere points per block
#define K2_NSPLIT  8
#define K2_NSLICE  (NN/K2_NSPLIT)        // 4096
#define K2_TILE    512

// Scratch (no allocations allowed) ------------------------------------------
__device__ float4       g_xyzp [BB*NN];   // (x,y,z, |p|^2)  for k_p2c
__device__ ulonglong4   g_xyzp2[BB*NN];   // {x,x},{y,y},{z,z},{w,w} packed pairs
__device__ float4       g_ctrp [BB*NCC];  // centers packed (x,y,z,|c|^2)
__device__ unsigned int g_minsq[BB*MM];   // min squared dist as uint bits (>=0)
__device__ float        g_acc[4];         // [b]=sum|min(r-cd,0)| ; [2+b]=sum max cd

// ---------------------------------------------------------------------------
__device__ __forceinline__ unsigned long long pack2(float a, float b) {
    unsigned long long r;
    asm("mov.b64 %0, {%1, %2};" : "=l"(r) : "f"(a), "f"(b));
    return r;
}

// 3x fma.rn.f32x2 (packed dot over 2 sphere points vs 1 xyz point) + 2 scalar mins.
// t = ax*x + w ; t += ay*y ; t += az*z ;  mn = min(mn, t) per half.
#define STEP2(mnlo, mnhi, AX, AY, AZ, XX, YY, ZZ, WW)                 \
    asm("{\n\t"                                                       \
        ".reg .b64 t;\n\t"                                            \
        ".reg .f32 tl, th;\n\t"                                       \
        "fma.rn.f32x2 t, %2, %5, %8;\n\t"                             \
        "fma.rn.f32x2 t, %3, %6, t;\n\t"                              \
        "fma.rn.f32x2 t, %4, %7, t;\n\t"                              \
        "mov.b64 {tl, th}, t;\n\t"                                    \
        "min.f32 %0, %0, tl;\n\t"                                     \
        "min.f32 %1, %1, th;\n\t"                                     \
        "}"                                                           \
        : "+f"(mnlo), "+f"(mnhi)                                      \
        : "l"(AX), "l"(AY), "l"(AZ), "l"(XX), "l"(YY), "l"(ZZ), "l"(WW))

__inline__ __device__ float blockReduceSum(float v) {
    __shared__ float sw[32];
    #pragma unroll
    for (int o = 16; o > 0; o >>= 1) v += __shfl_down_sync(0xffffffffu, v, o);
    int lane = threadIdx.x & 31, w = threadIdx.x >> 5;
    if (lane == 0) sw[w] = v;
    __syncthreads();
    int nw = blockDim.x >> 5;
    v = (threadIdx.x < nw) ? sw[threadIdx.x] : 0.0f;
    if (w == 0) {
        #pragma unroll
        for (int o = 16; o > 0; o >>= 1) v += __shfl_down_sync(0xffffffffu, v, o);
    }
    return v;
}

// Pack inputs + init scratch --------------------------------------------------
__global__ void k_prep(const float* __restrict__ xyz, const float* __restrict__ ctr) {
    int i = blockIdx.x * blockDim.x + threadIdx.x;
    if (i < BB*NN) {
        float x = xyz[3*i+0], y = xyz[3*i+1], z = xyz[3*i+2];
        float w = x*x + y*y + z*z;
        g_xyzp[i]  = make_float4(x, y, z, w);
        ulonglong4 u;
        u.x = pack2(x, x); u.y = pack2(y, y); u.z = pack2(z, z); u.w = pack2(w, w);
        g_xyzp2[i] = u;
        g_minsq[i] = 0x7F800000u;   // +inf
    }
    if (i < BB*NCC) {
        float x = ctr[3*i+0], y = ctr[3*i+1], z = ctr[3*i+2];
        g_ctrp[i] = make_float4(x, y, z, x*x + y*y + z*z);
    }
    if (i < 4) g_acc[i] = 0.0f;
}

// Part 1: point -> nearest center, accumulate |min(r - cd, 0)| ----------------
__global__ void k_p2c(const float* __restrict__ radius) {
    __shared__ float4 shc[NCC];
    const int b = blockIdx.y;
    const int n = blockIdx.x * blockDim.x + threadIdx.x;
    for (int i = threadIdx.x; i < NCC; i += blockDim.x)
        shc[i] = g_ctrp[b*NCC + i];
    __syncthreads();

    float4 q = g_xyzp[b*NN + n];
    float ax = -2.0f*q.x, ay = -2.0f*q.y, az = -2.0f*q.z;
    float tmin = CUDART_INF_F;
    int idx = 0;
    #pragma unroll 4
    for (int c = 0; c < NCC; ++c) {
        float4 p = shc[c];
        float t = fmaf(ax, p.x, p.w);
        t = fmaf(ay, p.y, t);
        t = fmaf(az, p.z, t);
        if (t < tmin) { tmin = t; idx = c; }   // strict < : first-min == jnp.argmin
    }
    float cd = sqrtf(fmaxf(tmin + q.w, 1e-12f));
    float contrib = fmaxf(cd - radius[b*NCC + idx], 0.0f); // == |min(r-cd,0)|
    float s = blockReduceSum(contrib);
    if (threadIdx.x == 0) atomicAdd(&g_acc[b], s);
}

// Part 2 (dominant): sphere point -> min over xyz, packed f32x2 ----------------
__global__ void __launch_bounds__(K2_THREADS)
k_sp2p(const float* __restrict__ sp) {
    __shared__ ulonglong4 shp[K2_TILE];       // 16 KB
    const int b     = blockIdx.z;
    const int nbase = blockIdx.y * K2_NSLICE;
    const int mbase = blockIdx.x * K2_TM;
    const int tid   = threadIdx.x;

    unsigned long long ax2[K2_R/2], ay2[K2_R/2], az2[K2_R/2];
    float nq[K2_R], mn[K2_R];
    #pragma unroll
    for (int r2 = 0; r2 < K2_R/2; ++r2) {
        int m0 = mbase + tid*K2_R + 2*r2;
        const float* p0 = sp + ((long long)b*MM + m0) * 3;
        float x0 = p0[0], y0 = p0[1], z0 = p0[2];
        float x1 = p0[3], y1 = p0[4], z1 = p0[5];
        ax2[r2] = pack2(-2.0f*x0, -2.0f*x1);
        ay2[r2] = pack2(-2.0f*y0, -2.0f*y1);
        az2[r2] = pack2(-2.0f*z0, -2.0f*z1);
        nq[2*r2+0] = x0*x0 + y0*y0 + z0*z0;
        nq[2*r2+1] = x1*x1 + y1*y1 + z1*z1;
        mn[2*r2+0] = CUDART_INF_F;
        mn[2*r2+1] = CUDART_INF_F;
    }

    const ulonglong4* xb = g_xyzp2 + b*NN + nbase;
    for (int jt = 0; jt < K2_NSLICE; jt += K2_TILE) {
        for (int i = tid; i < K2_TILE; i += K2_THREADS)
            shp[i] = xb[jt + i];
        __syncthreads();
        #pragma unroll 2
        for (int j = 0; j < K2_TILE; ++j) {
            ulonglong4 p = shp[j];            // 2x LDS.128, broadcast (N=1)
            #pragma unroll
            for (int r2 = 0; r2 < K2_R/2; ++r2)
                STEP2(mn[2*r2], mn[2*r2+1],
                      ax2[r2], ay2[r2], az2[r2],
                      p.x, p.y, p.z, p.w);
        }
        __syncthreads();
    }

    #pragma unroll
    for (int r = 0; r < K2_R; ++r) {
        float sq = fmaxf(mn[r] + nq[r], 0.0f);   // >=0 so uint order == float order
        atomicMin(&g_minsq[b*MM + mbase + tid*K2_R + r], __float_as_uint(sq));
    }
}

// Part 2 epilogue: max over S per center, sum over centers --------------------
__global__ void k_c2p() {
    const int b = blockIdx.y;
    const int c = blockIdx.x * blockDim.x + threadIdx.x;
    const unsigned int* base = g_minsq + b*MM + c*SS;
    float mx = 0.0f;
    #pragma unroll
    for (int s = 0; s < SS; ++s) {
        float sq = __uint_as_float(base[s]);
        mx = fmaxf(mx, sqrtf(fmaxf(sq, 1e-12f)));
    }
    float s = blockReduceSum(mx);
    if (threadIdx.x == 0) atomicAdd(&g_acc[2 + b], s);
}

// Final scalar ----------------------------------------------------------------
__global__ void k_final(float* out) {
    float r = 0.0f;
    #pragma unroll
    for (int b = 0; b < BB; ++b)
        r += g_acc[b] * (1.0f/NN) + g_acc[2 + b] * (1.0f/NCC);
    out[0] = r * (1.0f/BB);
}

// ---------------------------------------------------------------------------
extern "C" void kernel_launch(void* const* d_in, const int* in_sizes, int n_in,
                              void* d_out, int out_size) {
    const float* centers = (const float*)d_in[0];
    const float* radius  = (const float*)d_in[1];
    const float* xyz     = (const float*)d_in[2];
    const float* sp      = (const float*)d_in[3];
    float* out = (float*)d_out;

    k_prep<<<(BB*NN)/256, 256>>>(xyz, centers);
    k_p2c<<<dim3(NN/256, BB), 256>>>(radius);
    k_sp2p<<<dim3(MM/K2_TM, K2_NSPLIT, BB), K2_THREADS>>>(sp);
    k_c2p<<<dim3(NCC/256, BB), 256>>>();
    k_final<<<1, 1>>>(out);
}